// round 1
// baseline (speedup 1.0000x reference)
#include <cuda_runtime.h>
#include <math.h>

// Problem constants (fixed by the reference setup_inputs)
#define B   16
#define C   512
#define NTOK 4096      // h*w = 64*64
#define S   8
#define BS  (B*S)      // 128

// Scratch: attention logits A[b][s][n]  (2 MB, fits L2) + softmax stats
__device__ float g_A[B * S * NTOK];
__device__ float g_m[BS];
__device__ float g_l[BS];

// ---------------------------------------------------------------------------
// K1: A[b,s,n] = sum_c x[b,c,n] * Wk[s,c]
// grid: (NTOK/256, B), block: 256 threads, thread <-> one n
// Wk staged in smem transposed to [c][s] so each c-iter is 2x float4 broadcast.
// ---------------------------------------------------------------------------
__global__ void __launch_bounds__(256) k1_logits(const float* __restrict__ x,
                                                 const float* __restrict__ Wk) {
    __shared__ float wk[C * S];               // wk[c*8 + s]
    const int tid = threadIdx.x;
    for (int i = tid; i < C * S; i += 256) {
        int s = i / C, c = i % C;
        wk[c * S + s] = Wk[i];
    }
    __syncthreads();

    const int b = blockIdx.y;
    const int n = blockIdx.x * 256 + tid;
    const float* xp = x + (size_t)b * C * NTOK + n;

    float acc0 = 0.f, acc1 = 0.f, acc2 = 0.f, acc3 = 0.f;
    float acc4 = 0.f, acc5 = 0.f, acc6 = 0.f, acc7 = 0.f;
    const float4* wk4 = (const float4*)wk;

#pragma unroll 4
    for (int c = 0; c < C; c++) {
        float xv = xp[(size_t)c * NTOK];
        float4 w0 = wk4[c * 2 + 0];
        float4 w1 = wk4[c * 2 + 1];
        acc0 = fmaf(xv, w0.x, acc0);
        acc1 = fmaf(xv, w0.y, acc1);
        acc2 = fmaf(xv, w0.z, acc2);
        acc3 = fmaf(xv, w0.w, acc3);
        acc4 = fmaf(xv, w1.x, acc4);
        acc5 = fmaf(xv, w1.y, acc5);
        acc6 = fmaf(xv, w1.z, acc6);
        acc7 = fmaf(xv, w1.w, acc7);
    }

    float* Ap = g_A + (size_t)b * S * NTOK + n;
    Ap[0 * NTOK] = acc0;  Ap[1 * NTOK] = acc1;
    Ap[2 * NTOK] = acc2;  Ap[3 * NTOK] = acc3;
    Ap[4 * NTOK] = acc4;  Ap[5 * NTOK] = acc5;
    Ap[6 * NTOK] = acc6;  Ap[7 * NTOK] = acc7;
}

// ---------------------------------------------------------------------------
// K2: per (b,s): m = max_n A, l = sum_n exp(A - m)
// grid: 128 blocks (one per (b,s)), block 256 threads
// ---------------------------------------------------------------------------
__global__ void __launch_bounds__(256) k2_stats() {
    const int bs = blockIdx.x;
    const float* Ap = g_A + (size_t)bs * NTOK;
    const int tid = threadIdx.x;

    __shared__ float red[256];

    float mx = -INFINITY;
    for (int i = tid; i < NTOK; i += 256) mx = fmaxf(mx, Ap[i]);
    red[tid] = mx;
    __syncthreads();
    for (int o = 128; o > 0; o >>= 1) {
        if (tid < o) red[tid] = fmaxf(red[tid], red[tid + o]);
        __syncthreads();
    }
    const float m = red[0];
    __syncthreads();

    float sum = 0.f;
    for (int i = tid; i < NTOK; i += 256) sum += expf(Ap[i] - m);
    red[tid] = sum;
    __syncthreads();
    for (int o = 128; o > 0; o >>= 1) {
        if (tid < o) red[tid] += red[tid + o];
        __syncthreads();
    }
    if (tid == 0) {
        g_m[bs] = m;
        g_l[bs] = red[0];
    }
}

// ---------------------------------------------------------------------------
// K3: per (b,n): p[s] = exp(A-m)/l; w[s] = p[s]/(1e-9 + sum_s p);
//     out[b,c,n] = relu(x[b,c,n] + sum_s w[s]*Wv[c,s])
// grid: (NTOK/256, B), block: 256 threads, thread <-> one n
// ---------------------------------------------------------------------------
__global__ void __launch_bounds__(256) k3_out(const float* __restrict__ x,
                                              const float* __restrict__ Wv,
                                              float* __restrict__ out) {
    __shared__ float wv[C * S];               // Wv is already [c][s] row-major
    const int tid = threadIdx.x;
    for (int i = tid; i < C * S; i += 256) wv[i] = Wv[i];
    __syncthreads();

    const int b = blockIdx.y;
    const int n = blockIdx.x * 256 + tid;

    float p[S];
    float psum = 0.f;
#pragma unroll
    for (int s = 0; s < S; s++) {
        const int bs = b * S + s;
        float a = g_A[(size_t)bs * NTOK + n];
        p[s] = expf(a - g_m[bs]) / g_l[bs];
        psum += p[s];
    }
    const float inv = 1.0f / (1e-9f + psum);
#pragma unroll
    for (int s = 0; s < S; s++) p[s] *= inv;

    const float* xp = x + (size_t)b * C * NTOK + n;
    float* op = out + (size_t)b * C * NTOK + n;
    const float4* wv4 = (const float4*)wv;

#pragma unroll 4
    for (int c = 0; c < C; c++) {
        float xv = xp[(size_t)c * NTOK];
        float4 v0 = wv4[c * 2 + 0];
        float4 v1 = wv4[c * 2 + 1];
        float o = xv;
        o = fmaf(p[0], v0.x, o);
        o = fmaf(p[1], v0.y, o);
        o = fmaf(p[2], v0.z, o);
        o = fmaf(p[3], v0.w, o);
        o = fmaf(p[4], v1.x, o);
        o = fmaf(p[5], v1.y, o);
        o = fmaf(p[6], v1.z, o);
        o = fmaf(p[7], v1.w, o);
        op[(size_t)c * NTOK] = fmaxf(o, 0.f);
    }
}

// ---------------------------------------------------------------------------
extern "C" void kernel_launch(void* const* d_in, const int* in_sizes, int n_in,
                              void* d_out, int out_size) {
    const float* x  = (const float*)d_in[0];
    const float* Wk = (const float*)d_in[1];
    const float* Wv = (const float*)d_in[2];
    float* out = (float*)d_out;

    dim3 grid1(NTOK / 256, B);
    k1_logits<<<grid1, 256>>>(x, Wk);
    k2_stats<<<BS, 256>>>();
    dim3 grid3(NTOK / 256, B);
    k3_out<<<grid3, 256>>>(x, Wv, out);
}

// round 2
// speedup vs baseline: 2.4578x; 2.4578x over previous
#include <cuda_runtime.h>
#include <math.h>

// Problem constants (fixed by the reference setup_inputs)
#define B      16
#define C      512
#define NTOK   4096      // h*w
#define S      8
#define BS     (B*S)     // 128
#define CSPLIT 4
#define CCHUNK (C/CSPLIT) // 128

// Scratch (device globals — no allocation allowed)
__device__ float g_Ap[CSPLIT][BS * NTOK];  // partial logits, 8 MB
__device__ float g_A [BS * NTOK];          // combined logits, 2 MB
__device__ float g_P [BS * NTOK];          // exp(a - m), 2 MB
__device__ float g_invl[BS];               // 1 / sumexp

// ---------------------------------------------------------------------------
// K1: partial A[b,s,n] = sum_{c in chunk} x[b,c,n] * Wk[s,c]
// grid: (NTOK/1024, CSPLIT, B), block 256. Thread = 4 consecutive n (float4).
// ---------------------------------------------------------------------------
__global__ void __launch_bounds__(256) k1_logits(const float* __restrict__ x,
                                                 const float* __restrict__ Wk) {
    __shared__ float wk[CCHUNK * S];          // wk[ci*8 + s]
    const int tid = threadIdx.x;
    const int csel = blockIdx.y;
    const int b = blockIdx.z;
    const int c0 = csel * CCHUNK;

    for (int i = tid; i < CCHUNK * S; i += 256) {
        int ci = i >> 3, s = i & 7;
        wk[i] = Wk[s * C + c0 + ci];
    }
    __syncthreads();

    const int n0 = (blockIdx.x * 256 + tid) * 4;
    const float* xp = x + ((size_t)b * C + c0) * NTOK + n0;

    float4 acc[S];
#pragma unroll
    for (int s = 0; s < S; s++) acc[s] = make_float4(0.f, 0.f, 0.f, 0.f);

#pragma unroll 4
    for (int ci = 0; ci < CCHUNK; ci++) {
        float4 xv = *(const float4*)(xp + (size_t)ci * NTOK);
#pragma unroll
        for (int s = 0; s < S; s++) {
            float w = wk[ci * S + s];
            acc[s].x = fmaf(w, xv.x, acc[s].x);
            acc[s].y = fmaf(w, xv.y, acc[s].y);
            acc[s].z = fmaf(w, xv.z, acc[s].z);
            acc[s].w = fmaf(w, xv.w, acc[s].w);
        }
    }

    float* Ap = g_Ap[csel] + (size_t)b * S * NTOK + n0;
#pragma unroll
    for (int s = 0; s < S; s++)
        *(float4*)(Ap + (size_t)s * NTOK) = acc[s];
}

// ---------------------------------------------------------------------------
// K2: per (b,s): combine partials, m = max, P = exp(a-m), invl = 1/sum(P)
// grid: 128 blocks (one per bs), block 256
// ---------------------------------------------------------------------------
__global__ void __launch_bounds__(256) k2_stats() {
    const int bs = blockIdx.x;
    const int tid = threadIdx.x;
    const size_t base = (size_t)bs * NTOK;

    __shared__ float red[256];

    // pass 1: combine partials -> g_A, track max
    float mx = -INFINITY;
    for (int i4 = tid; i4 < NTOK / 4; i4 += 256) {
        float4 a0 = *(const float4*)(g_Ap[0] + base + i4 * 4);
        float4 a1 = *(const float4*)(g_Ap[1] + base + i4 * 4);
        float4 a2 = *(const float4*)(g_Ap[2] + base + i4 * 4);
        float4 a3 = *(const float4*)(g_Ap[3] + base + i4 * 4);
        float4 a;
        a.x = a0.x + a1.x + a2.x + a3.x;
        a.y = a0.y + a1.y + a2.y + a3.y;
        a.z = a0.z + a1.z + a2.z + a3.z;
        a.w = a0.w + a1.w + a2.w + a3.w;
        *(float4*)(g_A + base + i4 * 4) = a;
        mx = fmaxf(mx, fmaxf(fmaxf(a.x, a.y), fmaxf(a.z, a.w)));
    }
    red[tid] = mx;
    __syncthreads();
    for (int o = 128; o > 0; o >>= 1) {
        if (tid < o) red[tid] = fmaxf(red[tid], red[tid + o]);
        __syncthreads();
    }
    const float m = red[0];
    __syncthreads();

    // pass 2: P = exp(a - m), sum
    float sum = 0.f;
    for (int i4 = tid; i4 < NTOK / 4; i4 += 256) {
        float4 a = *(const float4*)(g_A + base + i4 * 4);
        float4 e;
        e.x = expf(a.x - m);
        e.y = expf(a.y - m);
        e.z = expf(a.z - m);
        e.w = expf(a.w - m);
        *(float4*)(g_P + base + i4 * 4) = e;
        sum += e.x + e.y + e.z + e.w;
    }
    red[tid] = sum;
    __syncthreads();
    for (int o = 128; o > 0; o >>= 1) {
        if (tid < o) red[tid] += red[tid + o];
        __syncthreads();
    }
    if (tid == 0) g_invl[bs] = 1.0f / red[0];
}

// ---------------------------------------------------------------------------
// K3: out[b,c,n] = relu(x[b,c,n] + sum_s w[s,n]*Wv[c,s])
//     w[s,n] = (P[bs,n]*invl[bs]) / (1e-9 + sum_s P[bs,n]*invl[bs])
// grid: (NTOK/1024, C/32, B), block 256. Thread = 4 n (float4), 32 c.
// ---------------------------------------------------------------------------
#define K3C 32
__global__ void __launch_bounds__(256) k3_out(const float* __restrict__ x,
                                              const float* __restrict__ Wv,
                                              float* __restrict__ out) {
    __shared__ float wv[K3C * S];             // Wv slice [c][s], row-major
    const int tid = threadIdx.x;
    const int b = blockIdx.z;
    const int c0 = blockIdx.y * K3C;

    // stage Wv chunk (256 contiguous floats)
    wv[tid] = Wv[c0 * S + tid];
    __syncthreads();

    const int n0 = (blockIdx.x * 256 + tid) * 4;

    // renormalized weights in registers: p[s] for this thread's 4 n
    float4 p[S];
    float4 psum = make_float4(1e-9f, 1e-9f, 1e-9f, 1e-9f);
#pragma unroll
    for (int s = 0; s < S; s++) {
        const int bs = b * S + s;
        float4 e = *(const float4*)(g_P + (size_t)bs * NTOK + n0);
        float il = g_invl[bs];
        p[s].x = e.x * il; p[s].y = e.y * il;
        p[s].z = e.z * il; p[s].w = e.w * il;
        psum.x += p[s].x; psum.y += p[s].y;
        psum.z += p[s].z; psum.w += p[s].w;
    }
    float4 inv;
    inv.x = 1.0f / psum.x; inv.y = 1.0f / psum.y;
    inv.z = 1.0f / psum.z; inv.w = 1.0f / psum.w;
#pragma unroll
    for (int s = 0; s < S; s++) {
        p[s].x *= inv.x; p[s].y *= inv.y;
        p[s].z *= inv.z; p[s].w *= inv.w;
    }

    const float* xp = x + ((size_t)b * C + c0) * NTOK + n0;
    float* op = out + ((size_t)b * C + c0) * NTOK + n0;

#pragma unroll 4
    for (int ci = 0; ci < K3C; ci++) {
        float4 xv = *(const float4*)(xp + (size_t)ci * NTOK);
        float4 o = xv;
#pragma unroll
        for (int s = 0; s < S; s++) {
            float w = wv[ci * S + s];
            o.x = fmaf(p[s].x, w, o.x);
            o.y = fmaf(p[s].y, w, o.y);
            o.z = fmaf(p[s].z, w, o.z);
            o.w = fmaf(p[s].w, w, o.w);
        }
        o.x = fmaxf(o.x, 0.f); o.y = fmaxf(o.y, 0.f);
        o.z = fmaxf(o.z, 0.f); o.w = fmaxf(o.w, 0.f);
        *(float4*)(op + (size_t)ci * NTOK) = o;
    }
}

// ---------------------------------------------------------------------------
extern "C" void kernel_launch(void* const* d_in, const int* in_sizes, int n_in,
                              void* d_out, int out_size) {
    const float* x  = (const float*)d_in[0];
    const float* Wk = (const float*)d_in[1];
    const float* Wv = (const float*)d_in[2];
    float* out = (float*)d_out;

    dim3 g1(NTOK / 1024, CSPLIT, B);
    k1_logits<<<g1, 256>>>(x, Wk);
    k2_stats<<<BS, 256>>>();
    dim3 g3(NTOK / 1024, C / K3C, B);
    k3_out<<<g3, 256>>>(x, Wv, out);
}